// round 7
// baseline (speedup 1.0000x reference)
#include <cuda_runtime.h>
#include <cuda_fp16.h>

// ---------------- problem constants ----------------
#define BB   2
#define CC   24
#define KQ   7
#define KK   49
#define HH   256
#define WW   256
#define CO   1176          // CC*KK
#define PLANE 65536
#define NPIX  131072

#define LOG2E 1.4426950408889634f

// ---------------- device scratch ----------------
__device__ __half g_E[(size_t)CO * NPIX];   // unnormalized exp(logits), fp16, PLANE-MAJOR
__device__ float g_Spart[(size_t)CC * NPIX];
__device__ float g_Sinv[NPIX];
__device__ float g_lat[BB * CC * PLANE];
__device__ float g_dA[BB * CC * PLANE];
__device__ float g_dB[BB * CC * PLANE];

// ---------------- packed f32x2 helpers (k_softmax only) ----------------
typedef unsigned long long ull;
__device__ __forceinline__ ull pk2(float lo, float hi) {
    ull r; asm("mov.b64 %0, {%1, %2};" : "=l"(r) : "f"(lo), "f"(hi)); return r;
}
__device__ __forceinline__ void fma2(ull& d, ull a, ull b) {
    asm("fma.rn.f32x2 %0, %1, %2, %0;" : "+l"(d) : "l"(a), "l"(b));
}
__device__ __forceinline__ void add2(ull& d, ull a) {
    asm("add.rn.f32x2 %0, %0, %1;" : "+l"(d) : "l"(a));
}
__device__ __forceinline__ void unpk2(float& lo, float& hi, ull v) {
    asm("mov.b64 {%0, %1}, %2;" : "=f"(lo), "=f"(hi) : "l"(v));
}
__device__ __forceinline__ float ex2(float x) {
    float r; asm("ex2.approx.f32 %0, %1;" : "=f"(r) : "f"(x)); return r;
}
__device__ __forceinline__ float rcpf(float x) {
    float r; asm("rcp.approx.f32 %0, %1;" : "=f"(r) : "f"(x)); return r;
}

// ================= K1: depth_latent = conv3x3(depth; 1 -> 24) =================
__global__ void k_lat(const float* __restrict__ depth,
                      const float* __restrict__ w_dp,
                      const float* __restrict__ b_dp) {
    __shared__ float sD[3][WW + 2];
    __shared__ float sW[CC * 9];
    __shared__ float sB[CC];
    const int bid = blockIdx.x;
    const int b = bid >> 8, y = bid & 255;
    const int tid = threadIdx.x;

    for (int i = tid; i < CC * 9; i += blockDim.x) sW[i] = w_dp[i];
    if (tid < CC) sB[tid] = b_dp[tid];

    const float* dp = depth + (size_t)b * PLANE;
    for (int r = 0; r < 3; r++) {
        const int yy = y + r - 1;
        for (int xx = tid; xx < WW + 2; xx += blockDim.x) {
            const int gx = xx - 1;
            sD[r][xx] = (yy >= 0 && yy < HH && gx >= 0 && gx < WW) ? dp[yy * WW + gx] : 0.f;
        }
    }
    __syncthreads();

    float p[9];
#pragma unroll
    for (int r = 0; r < 3; r++)
#pragma unroll
        for (int cx = 0; cx < 3; cx++) p[r * 3 + cx] = sD[r][tid + cx];

    for (int co = 0; co < CC; co++) {
        float acc = sB[co];
#pragma unroll
        for (int j = 0; j < 9; j++) acc = fmaf(sW[co * 9 + j], p[j], acc);
        g_lat[((size_t)(b * CC + co) * HH + y) * WW + tid] = acc;
    }
}

// ================= K2: logits conv (3->1176) + exp (fp16 out) + partial sums ==========
// grid = (BB*HH/2 row-pairs, CC channels). Thread t: row ri = t>>6, pixels x0..x0+3.
__global__ __launch_bounds__(128) void k_softmax(const float* __restrict__ tex,
                                                 const float* __restrict__ w_kp,
                                                 const float* __restrict__ b_kp) {
    __shared__ __align__(16) float2 sW2[KK * 28];
    __shared__ float sB[KK];
    __shared__ float sT[3][4][WW + 2];

    const int bid = blockIdx.x;
    const int c = blockIdx.y;
    const int b = bid >> 7;
    const int y0 = (bid & 127) * 2;
    const int tid = threadIdx.x;
    const int ri = tid >> 6;
    const int x0 = (tid & 63) * 4;

    for (int i = tid; i < KK * 28; i += 128) {
        const int o = i / 28, j = i - o * 28;
        const float w = (j < 27) ? w_kp[(size_t)(c * KK + o) * 27 + j] * LOG2E : 0.f;
        sW2[i] = make_float2(w, w);
    }
    if (tid < KK) sB[tid] = b_kp[c * KK + tid] * LOG2E;

    for (int ch = 0; ch < 3; ch++) {
        const float* tp = tex + (size_t)(b * 3 + ch) * PLANE;
        for (int rr = 0; rr < 4; rr++) {
            const int yy = y0 + rr - 1;
            for (int xx = tid; xx < WW + 2; xx += blockDim.x) {
                const int gx = xx - 1;
                sT[ch][rr][xx] = (yy >= 0 && yy < HH && gx >= 0 && gx < WW) ? tp[yy * WW + gx] : 0.f;
            }
        }
    }
    __syncthreads();

    ull PK[3][3][5];
#pragma unroll
    for (int ch = 0; ch < 3; ch++)
#pragma unroll
        for (int r = 0; r < 3; r++) {
            float v[6];
#pragma unroll
            for (int k = 0; k < 6; k++) v[k] = sT[ch][ri + r][x0 + k];
#pragma unroll
            for (int k = 0; k < 5; k++) PK[ch][r][k] = pk2(v[k], v[k + 1]);
        }
    const ull ZP = pk2(0.f, 0.f);

    float S0 = 0.f, S1 = 0.f, S2 = 0.f, S3 = 0.f;
    const size_t pixbase = (size_t)b * PLANE + (size_t)(y0 + ri) * WW + x0;

#pragma unroll 1
    for (int ol = 0; ol < KK; ol++) {
        const float4* w4 = reinterpret_cast<const float4*>(&sW2[ol * 28]);
        const float bb = sB[ol];
        ull aA0 = pk2(bb, bb), aA1 = ZP;
        ull aB0 = pk2(bb, bb), aB1 = ZP;
#pragma unroll
        for (int q = 0; q < 14; q++) {
            const float4 v = w4[q];
            const ull wp0 = pk2(v.x, v.y);
            const ull wp1 = pk2(v.z, v.w);
            const int j0 = 2 * q, j1 = 2 * q + 1;
            const ull pA0 = (j0 < 27) ? PK[j0 / 9][(j0 % 9) / 3][j0 % 3] : ZP;
            const ull pB0 = (j0 < 27) ? PK[j0 / 9][(j0 % 9) / 3][j0 % 3 + 2] : ZP;
            const ull pA1 = (j1 < 27) ? PK[j1 / 9][(j1 % 9) / 3][j1 % 3] : ZP;
            const ull pB1 = (j1 < 27) ? PK[j1 / 9][(j1 % 9) / 3][j1 % 3 + 2] : ZP;
            fma2(aA0, wp0, pA0);
            fma2(aB0, wp0, pB0);
            fma2(aA1, wp1, pA1);
            fma2(aB1, wp1, pB1);
        }
        add2(aA0, aA1);
        add2(aB0, aB1);
        float lA0, lA1, lB0, lB1;
        unpk2(lA0, lA1, aA0);
        unpk2(lB0, lB1, aB0);
        const float eA0 = ex2(lA0), eA1 = ex2(lA1);
        const float eB0 = ex2(lB0), eB1 = ex2(lB1);
        S0 += eA0; S1 += eA1; S2 += eB0; S3 += eB1;
        const __half2 hA = __floats2half2_rn(eA0, eA1);
        const __half2 hB = __floats2half2_rn(eB0, eB1);
        uint2 st;
        st.x = *reinterpret_cast<const unsigned int*>(&hA);
        st.y = *reinterpret_cast<const unsigned int*>(&hB);
        *reinterpret_cast<uint2*>(&g_E[(size_t)(c * KK + ol) * NPIX + pixbase]) = st;
    }
    float4 ps;
    ps.x = S0; ps.y = S1; ps.z = S2; ps.w = S3;
    *reinterpret_cast<float4*>(&g_Spart[(size_t)c * NPIX + pixbase]) = ps;
}

// ================= K2b: reduce 24 partials -> 1/S =================
__global__ void k_sinv() {
    const int idx = blockIdx.x * 256 + threadIdx.x;
    float s = 0.f;
#pragma unroll
    for (int c = 0; c < CC; c++) s += g_Spart[(size_t)c * NPIX + idx];
    g_Sinv[idx] = rcpf(s);
}

// ================= K3..K6: one diffusion iteration =================
// 256 threads, 2 px/thread (x0 = 2*(tid&127), row ri = tid>>7), 8 rows/block
// in 4 passes. E loads: __half2 (128B per warp-LDG), double-buffered across dy
// for structural MLP=7. Scalar fp32 math to keep regs low (occupancy).
#define RROWS 8
__global__ __launch_bounds__(256, 5) void k_diff(int srcSel, int dstSel) {
    __shared__ float sIn[RROWS + 6][WW + 10];   // sIn[r][xx] = in(y0+r-3, xx-3)
    const int tid = threadIdx.x;
    const int ty = blockIdx.x;
    const int c = blockIdx.y;
    const int b = blockIdx.z;
    const int y0 = ty * RROWS;
    const int ri = tid >> 7;
    const int x0 = (tid & 127) * 2;

    const float* src = (srcSel == 0) ? g_lat : (srcSel == 1 ? g_dA : g_dB);
    float* dst = (dstSel == 1) ? g_dA : g_dB;

    const float* sp = src + (size_t)(b * CC + c) * PLANE;
    for (int r = 0; r < RROWS + 6; r++) {
        const int yy = y0 + r - 3;
        for (int xx = tid; xx < WW + 9; xx += 256) {
            const int gx = xx - 3;
            sIn[r][xx] = (yy >= 0 && yy < HH && gx >= 0 && gx < WW) ? sp[yy * WW + gx] : 0.f;
        }
    }
    __syncthreads();

    const __half* Eb = g_E + (size_t)(c * KK) * NPIX + (size_t)b * PLANE;
    const float* Sb = g_Sinv + (size_t)b * PLANE;
    float* db = dst + (size_t)(b * CC + c) * PLANE;

#pragma unroll
    for (int pass = 0; pass < RROWS / 2; pass++) {
        const int ry = pass * 2 + ri;
        const size_t rowoff = (size_t)(y0 + ry) * WW + x0;
        const __half* Ep = Eb + rowoff;

        unsigned int e[2][KQ];
#pragma unroll
        for (int dx = 0; dx < KQ; dx++)
            e[0][dx] = *reinterpret_cast<const unsigned int*>(Ep + (size_t)dx * NPIX);

        float acc0 = 0.f, acc1 = 0.f, acc2 = 0.f, acc3 = 0.f;
#pragma unroll
        for (int dy = 0; dy < KQ; dy++) {
            if (dy < KQ - 1) {
#pragma unroll
                for (int dx = 0; dx < KQ; dx++)
                    e[(dy + 1) & 1][dx] = *reinterpret_cast<const unsigned int*>(
                        Ep + (size_t)((dy + 1) * KQ + dx) * NPIX);
            }
            float2 fp[4];
#pragma unroll
            for (int k = 0; k < 4; k++)
                fp[k] = *reinterpret_cast<const float2*>(&sIn[ry + dy][x0 + 2 * k]);
            const float* f = reinterpret_cast<const float*>(fp);   // f[0..7] = taps x0-3..x0+4
#pragma unroll
            for (int dx = 0; dx < KQ; dx++) {
                __half2 h;
                *reinterpret_cast<unsigned int*>(&h) = e[dy & 1][dx];
                const float2 ef = __half22float2(h);
                if (dx & 1) {
                    acc1 = fmaf(ef.x, f[dx], acc1);
                    acc3 = fmaf(ef.y, f[dx + 1], acc3);
                } else {
                    acc0 = fmaf(ef.x, f[dx], acc0);
                    acc2 = fmaf(ef.y, f[dx + 1], acc2);
                }
            }
        }
        const float2 si = *reinterpret_cast<const float2*>(Sb + rowoff);
        float2 o;
        o.x = (acc0 + acc1) * si.x;
        o.y = (acc2 + acc3) * si.y;
        *reinterpret_cast<float2*>(db + rowoff) = o;
    }
}

// ================= K7: 1x1 conv (24 -> 1) =================
__global__ void k_out(const float* __restrict__ w_td,
                      const float* __restrict__ b_td,
                      float* __restrict__ out) {
    const int bid = blockIdx.x;
    const int b = bid >> 8, y = bid & 255;
    const int tid = threadIdx.x;
    const float* sp = g_dB + (size_t)b * CC * PLANE + (size_t)y * WW + tid;
    float acc = b_td[0];
#pragma unroll
    for (int c = 0; c < CC; c++) acc = fmaf(w_td[c], sp[(size_t)c * PLANE], acc);
    out[(size_t)b * PLANE + (size_t)y * WW + tid] = acc;
}

// ================= host launcher =================
extern "C" void kernel_launch(void* const* d_in, const int* in_sizes, int n_in,
                              void* d_out, int out_size) {
    const float* depth   = (const float*)d_in[0];
    const float* texture = (const float*)d_in[1];
    const float* w_dp    = (const float*)d_in[2];
    const float* b_dp    = (const float*)d_in[3];
    const float* w_kp    = (const float*)d_in[4];
    const float* b_kp    = (const float*)d_in[5];
    const float* w_td    = (const float*)d_in[6];
    const float* b_td    = (const float*)d_in[7];
    float* out = (float*)d_out;

    k_lat<<<BB * HH, 256>>>(depth, w_dp, b_dp);

    dim3 gs(BB * HH / 2, CC);
    k_softmax<<<gs, 128>>>(texture, w_kp, b_kp);
    k_sinv<<<NPIX / 256, 256>>>();

    dim3 gd(HH / RROWS, CC, BB);
    k_diff<<<gd, 256>>>(0, 1);
    k_diff<<<gd, 256>>>(1, 2);
    k_diff<<<gd, 256>>>(2, 1);
    k_diff<<<gd, 256>>>(1, 2);

    k_out<<<BB * HH, 256>>>(w_td, b_td, out);
}

// round 8
// speedup vs baseline: 1.2625x; 1.2625x over previous
#include <cuda_runtime.h>
#include <cuda_fp16.h>

// ---------------- problem constants ----------------
#define BB   2
#define CC   24
#define KQ   7
#define KK   49
#define HH   256
#define WW   256
#define CO   1176          // CC*KK
#define PLANE 65536
#define NPIX  131072

#define LOG2E 1.4426950408889634f

// ---------------- device scratch ----------------
__device__ __half g_E[(size_t)CO * NPIX];   // unnormalized exp(logits), fp16, PLANE-MAJOR
__device__ float g_Spart[(size_t)CC * NPIX];
__device__ float g_Sinv[NPIX];
__device__ float g_lat[BB * CC * PLANE];
__device__ float g_dA[BB * CC * PLANE];
__device__ float g_dB[BB * CC * PLANE];

// ---------------- packed f32x2 helpers (k_softmax only) ----------------
typedef unsigned long long ull;
__device__ __forceinline__ ull pk2(float lo, float hi) {
    ull r; asm("mov.b64 %0, {%1, %2};" : "=l"(r) : "f"(lo), "f"(hi)); return r;
}
__device__ __forceinline__ void fma2(ull& d, ull a, ull b) {
    asm("fma.rn.f32x2 %0, %1, %2, %0;" : "+l"(d) : "l"(a), "l"(b));
}
__device__ __forceinline__ void add2(ull& d, ull a) {
    asm("add.rn.f32x2 %0, %0, %1;" : "+l"(d) : "l"(a));
}
__device__ __forceinline__ void unpk2(float& lo, float& hi, ull v) {
    asm("mov.b64 {%0, %1}, %2;" : "=f"(lo), "=f"(hi) : "l"(v));
}
__device__ __forceinline__ float ex2(float x) {
    float r; asm("ex2.approx.f32 %0, %1;" : "=f"(r) : "f"(x)); return r;
}
__device__ __forceinline__ float rcpf(float x) {
    float r; asm("rcp.approx.f32 %0, %1;" : "=f"(r) : "f"(x)); return r;
}

// ================= K1: depth_latent = conv3x3(depth; 1 -> 24) =================
__global__ void k_lat(const float* __restrict__ depth,
                      const float* __restrict__ w_dp,
                      const float* __restrict__ b_dp) {
    __shared__ float sD[3][WW + 2];
    __shared__ float sW[CC * 9];
    __shared__ float sB[CC];
    const int bid = blockIdx.x;
    const int b = bid >> 8, y = bid & 255;
    const int tid = threadIdx.x;

    for (int i = tid; i < CC * 9; i += blockDim.x) sW[i] = w_dp[i];
    if (tid < CC) sB[tid] = b_dp[tid];

    const float* dp = depth + (size_t)b * PLANE;
    for (int r = 0; r < 3; r++) {
        const int yy = y + r - 1;
        for (int xx = tid; xx < WW + 2; xx += blockDim.x) {
            const int gx = xx - 1;
            sD[r][xx] = (yy >= 0 && yy < HH && gx >= 0 && gx < WW) ? dp[yy * WW + gx] : 0.f;
        }
    }
    __syncthreads();

    float p[9];
#pragma unroll
    for (int r = 0; r < 3; r++)
#pragma unroll
        for (int cx = 0; cx < 3; cx++) p[r * 3 + cx] = sD[r][tid + cx];

    for (int co = 0; co < CC; co++) {
        float acc = sB[co];
#pragma unroll
        for (int j = 0; j < 9; j++) acc = fmaf(sW[co * 9 + j], p[j], acc);
        g_lat[((size_t)(b * CC + co) * HH + y) * WW + tid] = acc;
    }
}

// ================= K2: logits conv (3->1176) + exp (fp16 out) + partial sums ==========
__global__ __launch_bounds__(128) void k_softmax(const float* __restrict__ tex,
                                                 const float* __restrict__ w_kp,
                                                 const float* __restrict__ b_kp) {
    __shared__ __align__(16) float2 sW2[KK * 28];
    __shared__ float sB[KK];
    __shared__ float sT[3][4][WW + 2];

    const int bid = blockIdx.x;
    const int c = blockIdx.y;
    const int b = bid >> 7;
    const int y0 = (bid & 127) * 2;
    const int tid = threadIdx.x;
    const int ri = tid >> 6;
    const int x0 = (tid & 63) * 4;

    for (int i = tid; i < KK * 28; i += 128) {
        const int o = i / 28, j = i - o * 28;
        const float w = (j < 27) ? w_kp[(size_t)(c * KK + o) * 27 + j] * LOG2E : 0.f;
        sW2[i] = make_float2(w, w);
    }
    if (tid < KK) sB[tid] = b_kp[c * KK + tid] * LOG2E;

    for (int ch = 0; ch < 3; ch++) {
        const float* tp = tex + (size_t)(b * 3 + ch) * PLANE;
        for (int rr = 0; rr < 4; rr++) {
            const int yy = y0 + rr - 1;
            for (int xx = tid; xx < WW + 2; xx += blockDim.x) {
                const int gx = xx - 1;
                sT[ch][rr][xx] = (yy >= 0 && yy < HH && gx >= 0 && gx < WW) ? tp[yy * WW + gx] : 0.f;
            }
        }
    }
    __syncthreads();

    ull PK[3][3][5];
#pragma unroll
    for (int ch = 0; ch < 3; ch++)
#pragma unroll
        for (int r = 0; r < 3; r++) {
            float v[6];
#pragma unroll
            for (int k = 0; k < 6; k++) v[k] = sT[ch][ri + r][x0 + k];
#pragma unroll
            for (int k = 0; k < 5; k++) PK[ch][r][k] = pk2(v[k], v[k + 1]);
        }
    const ull ZP = pk2(0.f, 0.f);

    float S0 = 0.f, S1 = 0.f, S2 = 0.f, S3 = 0.f;
    const size_t pixbase = (size_t)b * PLANE + (size_t)(y0 + ri) * WW + x0;

#pragma unroll 1
    for (int ol = 0; ol < KK; ol++) {
        const float4* w4 = reinterpret_cast<const float4*>(&sW2[ol * 28]);
        const float bb = sB[ol];
        ull aA0 = pk2(bb, bb), aA1 = ZP;
        ull aB0 = pk2(bb, bb), aB1 = ZP;
#pragma unroll
        for (int q = 0; q < 14; q++) {
            const float4 v = w4[q];
            const ull wp0 = pk2(v.x, v.y);
            const ull wp1 = pk2(v.z, v.w);
            const int j0 = 2 * q, j1 = 2 * q + 1;
            const ull pA0 = (j0 < 27) ? PK[j0 / 9][(j0 % 9) / 3][j0 % 3] : ZP;
            const ull pB0 = (j0 < 27) ? PK[j0 / 9][(j0 % 9) / 3][j0 % 3 + 2] : ZP;
            const ull pA1 = (j1 < 27) ? PK[j1 / 9][(j1 % 9) / 3][j1 % 3] : ZP;
            const ull pB1 = (j1 < 27) ? PK[j1 / 9][(j1 % 9) / 3][j1 % 3 + 2] : ZP;
            fma2(aA0, wp0, pA0);
            fma2(aB0, wp0, pB0);
            fma2(aA1, wp1, pA1);
            fma2(aB1, wp1, pB1);
        }
        add2(aA0, aA1);
        add2(aB0, aB1);
        float lA0, lA1, lB0, lB1;
        unpk2(lA0, lA1, aA0);
        unpk2(lB0, lB1, aB0);
        const float eA0 = ex2(lA0), eA1 = ex2(lA1);
        const float eB0 = ex2(lB0), eB1 = ex2(lB1);
        S0 += eA0; S1 += eA1; S2 += eB0; S3 += eB1;
        const __half2 hA = __floats2half2_rn(eA0, eA1);
        const __half2 hB = __floats2half2_rn(eB0, eB1);
        uint2 st;
        st.x = *reinterpret_cast<const unsigned int*>(&hA);
        st.y = *reinterpret_cast<const unsigned int*>(&hB);
        *reinterpret_cast<uint2*>(&g_E[(size_t)(c * KK + ol) * NPIX + pixbase]) = st;
    }
    float4 ps;
    ps.x = S0; ps.y = S1; ps.z = S2; ps.w = S3;
    *reinterpret_cast<float4*>(&g_Spart[(size_t)c * NPIX + pixbase]) = ps;
}

// ================= K2b: reduce 24 partials -> 1/S =================
__global__ void k_sinv() {
    const int idx = blockIdx.x * 256 + threadIdx.x;
    float s = 0.f;
#pragma unroll
    for (int c = 0; c < CC; c++) s += g_Spart[(size_t)c * NPIX + idx];
    g_Sinv[idx] = rcpf(s);
}

// ================= K3..K6: one diffusion iteration (half2 math) =================
// 256 threads, 4 px/thread; block covers 8 rows x 256 px in 2 passes.
// Taps in smem as fp16, two parity copies (hO shifted by 1) so every pair is an
// aligned LDS.32/64. Inner op: HFMA2 per (dx, pixel-pair). 7 dx-accumulators per
// pair keep half chains <= 7 long; final reduce in fp32.
#define RROWS 8
#define SROW  (WW + 12)       // 268 halves per row (8B-aligned stride)
__global__ __launch_bounds__(256, 4) void k_diff(int srcSel, int dstSel) {
    __shared__ __half hE[RROWS + 6][SROW];   // hE[r][xx] = in(y0+r-3, xx-3), fp16
    __shared__ __half hO[RROWS + 6][SROW];   // hO[r][xx] = hE[r][xx+1]
    const int tid = threadIdx.x;
    const int ty = blockIdx.x;
    const int c = blockIdx.y;
    const int b = blockIdx.z;
    const int y0 = ty * RROWS;
    const int ri = tid >> 6;               // 0..3 row within pass
    const int x0 = (tid & 63) * 4;         // pixel quad base

    const float* src = (srcSel == 0) ? g_lat : (srcSel == 1 ? g_dA : g_dB);
    float* dst = (dstSel == 1) ? g_dA : g_dB;

    const float* sp = src + (size_t)(b * CC + c) * PLANE;
    for (int r = 0; r < RROWS + 6; r++) {
        const int yy = y0 + r - 3;
        for (int xx = tid; xx < WW + 8; xx += 256) {
            const int gx = xx - 3;
            const float v = (yy >= 0 && yy < HH && gx >= 0 && gx < WW) ? sp[yy * WW + gx] : 0.f;
            const __half h = __float2half_rn(v);
            hE[r][xx] = h;
            if (xx > 0) hO[r][xx - 1] = h;
        }
    }
    __syncthreads();

    const __half* Eb = g_E + (size_t)(c * KK) * NPIX + (size_t)b * PLANE;
    const float* Sb = g_Sinv + (size_t)b * PLANE;
    float* db = dst + (size_t)(b * CC + c) * PLANE;
    const __half2 Z2 = __floats2half2_rn(0.f, 0.f);

#pragma unroll
    for (int pass = 0; pass < 2; pass++) {
        const int ry = pass * 4 + ri;
        const size_t rowoff = (size_t)(y0 + ry) * WW + x0;
        const __half* Ep = Eb + rowoff;

        __half2 accA[KQ], accB[KQ];
#pragma unroll
        for (int k = 0; k < KQ; k++) { accA[k] = Z2; accB[k] = Z2; }

#pragma unroll
        for (int dy = 0; dy < KQ; dy++) {
            // taps: tE[j] = halves (x0+2j, x0+2j+1); tO[j] = halves (x0+2j+1, x0+2j+2)
            __half2 tE[5], tO[4];
            {
                const uint2 a = *reinterpret_cast<const uint2*>(&hE[ry + dy][x0]);
                const uint2 bq = *reinterpret_cast<const uint2*>(&hE[ry + dy][x0 + 4]);
                const unsigned int cq = *reinterpret_cast<const unsigned int*>(&hE[ry + dy][x0 + 8]);
                *reinterpret_cast<unsigned int*>(&tE[0]) = a.x;
                *reinterpret_cast<unsigned int*>(&tE[1]) = a.y;
                *reinterpret_cast<unsigned int*>(&tE[2]) = bq.x;
                *reinterpret_cast<unsigned int*>(&tE[3]) = bq.y;
                *reinterpret_cast<unsigned int*>(&tE[4]) = cq;
                const uint2 d = *reinterpret_cast<const uint2*>(&hO[ry + dy][x0]);
                const uint2 e2 = *reinterpret_cast<const uint2*>(&hO[ry + dy][x0 + 4]);
                *reinterpret_cast<unsigned int*>(&tO[0]) = d.x;
                *reinterpret_cast<unsigned int*>(&tO[1]) = d.y;
                *reinterpret_cast<unsigned int*>(&tO[2]) = e2.x;
                *reinterpret_cast<unsigned int*>(&tO[3]) = e2.y;
            }
#pragma unroll
            for (int dx = 0; dx < KQ; dx++) {
                const uint2 ev = *reinterpret_cast<const uint2*>(Ep + (size_t)(dy * KQ + dx) * NPIX);
                __half2 eA, eB;
                *reinterpret_cast<unsigned int*>(&eA) = ev.x;
                *reinterpret_cast<unsigned int*>(&eB) = ev.y;
                __half2 p1, p2;
                if ((dx & 1) == 0) { p1 = tE[dx >> 1]; p2 = tE[(dx >> 1) + 1]; }
                else               { p1 = tO[dx >> 1]; p2 = tO[(dx >> 1) + 1]; }
                accA[dx] = __hfma2(eA, p1, accA[dx]);
                accB[dx] = __hfma2(eB, p2, accB[dx]);
            }
        }
        // reduce: 7 -> 4 in half2 (chains stay short), then fp32
        __half2 rA0 = __hadd2(accA[0], accA[1]);
        __half2 rA1 = __hadd2(accA[2], accA[3]);
        __half2 rA2 = __hadd2(accA[4], accA[5]);
        __half2 rA3 = accA[6];
        __half2 rB0 = __hadd2(accB[0], accB[1]);
        __half2 rB1 = __hadd2(accB[2], accB[3]);
        __half2 rB2 = __hadd2(accB[4], accB[5]);
        __half2 rB3 = accB[6];
        const float2 fA0 = __half22float2(rA0), fA1 = __half22float2(rA1);
        const float2 fA2 = __half22float2(rA2), fA3 = __half22float2(rA3);
        const float2 fB0 = __half22float2(rB0), fB1 = __half22float2(rB1);
        const float2 fB2 = __half22float2(rB2), fB3 = __half22float2(rB3);
        const float sumA0 = (fA0.x + fA1.x) + (fA2.x + fA3.x);
        const float sumA1 = (fA0.y + fA1.y) + (fA2.y + fA3.y);
        const float sumB0 = (fB0.x + fB1.x) + (fB2.x + fB3.x);
        const float sumB1 = (fB0.y + fB1.y) + (fB2.y + fB3.y);
        const float4 si = *reinterpret_cast<const float4*>(Sb + rowoff);
        float4 o;
        o.x = sumA0 * si.x;
        o.y = sumA1 * si.y;
        o.z = sumB0 * si.z;
        o.w = sumB1 * si.w;
        *reinterpret_cast<float4*>(db + rowoff) = o;
    }
}

// ================= K7: 1x1 conv (24 -> 1) =================
__global__ void k_out(const float* __restrict__ w_td,
                      const float* __restrict__ b_td,
                      float* __restrict__ out) {
    const int bid = blockIdx.x;
    const int b = bid >> 8, y = bid & 255;
    const int tid = threadIdx.x;
    const float* sp = g_dB + (size_t)b * CC * PLANE + (size_t)y * WW + tid;
    float acc = b_td[0];
#pragma unroll
    for (int c = 0; c < CC; c++) acc = fmaf(w_td[c], sp[(size_t)c * PLANE], acc);
    out[(size_t)b * PLANE + (size_t)y * WW + tid] = acc;
}

// ================= host launcher =================
extern "C" void kernel_launch(void* const* d_in, const int* in_sizes, int n_in,
                              void* d_out, int out_size) {
    const float* depth   = (const float*)d_in[0];
    const float* texture = (const float*)d_in[1];
    const float* w_dp    = (const float*)d_in[2];
    const float* b_dp    = (const float*)d_in[3];
    const float* w_kp    = (const float*)d_in[4];
    const float* b_kp    = (const float*)d_in[5];
    const float* w_td    = (const float*)d_in[6];
    const float* b_td    = (const float*)d_in[7];
    float* out = (float*)d_out;

    k_lat<<<BB * HH, 256>>>(depth, w_dp, b_dp);

    dim3 gs(BB * HH / 2, CC);
    k_softmax<<<gs, 128>>>(texture, w_kp, b_kp);
    k_sinv<<<NPIX / 256, 256>>>();

    dim3 gd(HH / RROWS, CC, BB);
    k_diff<<<gd, 256>>>(0, 1);
    k_diff<<<gd, 256>>>(1, 2);
    k_diff<<<gd, 256>>>(2, 1);
    k_diff<<<gd, 256>>>(1, 2);

    k_out<<<BB * HH, 256>>>(w_td, b_td, out);
}

// round 9
// speedup vs baseline: 1.3997x; 1.1087x over previous
#include <cuda_runtime.h>
#include <cuda_fp16.h>

// ---------------- problem constants ----------------
#define BB   2
#define CC   24
#define KQ   7
#define KK   49
#define HH   256
#define WW   256
#define CO   1176          // CC*KK
#define PLANE 65536
#define NPIX  131072

#define LOG2E 1.4426950408889634f

// ---------------- device scratch ----------------
__device__ __half g_E[(size_t)CO * NPIX];   // unnormalized exp(logits), fp16, PLANE-MAJOR
__device__ float g_Spart[(size_t)CC * NPIX];
__device__ float g_Sinv[NPIX];
__device__ float g_lat[BB * CC * PLANE];
__device__ float g_dA[BB * CC * PLANE];
__device__ float g_dB[BB * CC * PLANE];

__device__ __forceinline__ float ex2(float x) {
    float r; asm("ex2.approx.f32 %0, %1;" : "=f"(r) : "f"(x)); return r;
}
__device__ __forceinline__ float rcpf(float x) {
    float r; asm("rcp.approx.f32 %0, %1;" : "=f"(r) : "f"(x)); return r;
}

// ================= K1: depth_latent = conv3x3(depth; 1 -> 24) =================
__global__ void k_lat(const float* __restrict__ depth,
                      const float* __restrict__ w_dp,
                      const float* __restrict__ b_dp) {
    __shared__ float sD[3][WW + 2];
    __shared__ float sW[CC * 9];
    __shared__ float sB[CC];
    const int bid = blockIdx.x;
    const int b = bid >> 8, y = bid & 255;
    const int tid = threadIdx.x;

    for (int i = tid; i < CC * 9; i += blockDim.x) sW[i] = w_dp[i];
    if (tid < CC) sB[tid] = b_dp[tid];

    const float* dp = depth + (size_t)b * PLANE;
    for (int r = 0; r < 3; r++) {
        const int yy = y + r - 1;
        for (int xx = tid; xx < WW + 2; xx += blockDim.x) {
            const int gx = xx - 1;
            sD[r][xx] = (yy >= 0 && yy < HH && gx >= 0 && gx < WW) ? dp[yy * WW + gx] : 0.f;
        }
    }
    __syncthreads();

    float p[9];
#pragma unroll
    for (int r = 0; r < 3; r++)
#pragma unroll
        for (int cx = 0; cx < 3; cx++) p[r * 3 + cx] = sD[r][tid + cx];

    for (int co = 0; co < CC; co++) {
        float acc = sB[co];
#pragma unroll
        for (int j = 0; j < 9; j++) acc = fmaf(sW[co * 9 + j], p[j], acc);
        g_lat[((size_t)(b * CC + co) * HH + y) * WW + tid] = acc;
    }
}

// ================= K2: logits conv (3->1176) via HFMA2 + exp + partial sums ==========
// grid = (BB*HH/2 row-pairs, CC channels). Thread t: row ri = t>>6, pixels x0..x0+3.
// Weights in smem as half2 (w,w), log2e-prescaled; patch pairs in half2 registers.
// One HFMA2 per (weight, pixel-pair): 2 MACs/lane -> 2x the fp32 FMA lane rate.
__global__ __launch_bounds__(128) void k_softmax(const float* __restrict__ tex,
                                                 const float* __restrict__ w_kp,
                                                 const float* __restrict__ b_kp) {
    __shared__ __align__(16) __half2 sW2h[KK * 28];   // (w,w) half2, 27 + 1 pad per output
    __shared__ float sB[KK];
    __shared__ __half sTh[3][4][WW + 2];

    const int bid = blockIdx.x;
    const int c = blockIdx.y;
    const int b = bid >> 7;
    const int y0 = (bid & 127) * 2;
    const int tid = threadIdx.x;
    const int ri = tid >> 6;
    const int x0 = (tid & 63) * 4;

    // stage weights: half2 (w,w) with w = w_kp * log2(e)
    for (int i = tid; i < KK * 28; i += 128) {
        const int o = i / 28, j = i - o * 28;
        const float w = (j < 27) ? w_kp[(size_t)(c * KK + o) * 27 + j] * LOG2E : 0.f;
        const __half h = __float2half_rn(w);
        sW2h[i] = __halves2half2(h, h);
    }
    if (tid < KK) sB[tid] = b_kp[c * KK + tid] * LOG2E;

    // stage texture rows y0-1 .. y0+2, fp16
    for (int ch = 0; ch < 3; ch++) {
        const float* tp = tex + (size_t)(b * 3 + ch) * PLANE;
        for (int rr = 0; rr < 4; rr++) {
            const int yy = y0 + rr - 1;
            for (int xx = tid; xx < WW + 2; xx += blockDim.x) {
                const int gx = xx - 1;
                const float v = (yy >= 0 && yy < HH && gx >= 0 && gx < WW) ? tp[yy * WW + gx] : 0.f;
                sTh[ch][rr][xx] = __float2half_rn(v);
            }
        }
    }
    __syncthreads();

    // patch pairs: PA[j] = taps for pixels (x0, x0+1); PB[j] for (x0+2, x0+3)
    __half2 PA[28], PB[28];
#pragma unroll
    for (int ch = 0; ch < 3; ch++)
#pragma unroll
        for (int r = 0; r < 3; r++) {
            __half v[6];
#pragma unroll
            for (int k = 0; k < 6; k++) v[k] = sTh[ch][ri + r][x0 + k];
#pragma unroll
            for (int cx = 0; cx < 3; cx++) {
                const int j = ch * 9 + r * 3 + cx;
                PA[j] = __halves2half2(v[cx], v[cx + 1]);
                PB[j] = __halves2half2(v[cx + 2], v[cx + 3]);
            }
        }
    PA[27] = __float2half2_rn(0.f);
    PB[27] = __float2half2_rn(0.f);

    float S0 = 0.f, S1 = 0.f, S2 = 0.f, S3 = 0.f;
    const size_t pixbase = (size_t)b * PLANE + (size_t)(y0 + ri) * WW + x0;
    const __half2 Z2 = __float2half2_rn(0.f);

#pragma unroll 1
    for (int ol = 0; ol < KK; ol++) {
        const uint4* wq = reinterpret_cast<const uint4*>(&sW2h[ol * 28]);  // 7 x uint4 (4 half2 each)
        __half2 a0 = Z2, a1 = Z2, a2 = Z2, a3 = Z2;
        __half2 b0 = Z2, b1 = Z2, b2 = Z2, b3 = Z2;
#pragma unroll
        for (int q = 0; q < 7; q++) {
            const uint4 u = wq[q];
            __half2 w0, w1, w2, w3;
            *reinterpret_cast<unsigned int*>(&w0) = u.x;
            *reinterpret_cast<unsigned int*>(&w1) = u.y;
            *reinterpret_cast<unsigned int*>(&w2) = u.z;
            *reinterpret_cast<unsigned int*>(&w3) = u.w;
            const int j = q * 4;
            a0 = __hfma2(w0, PA[j],     a0);  b0 = __hfma2(w0, PB[j],     b0);
            a1 = __hfma2(w1, PA[j + 1], a1);  b1 = __hfma2(w1, PB[j + 1], b1);
            a2 = __hfma2(w2, PA[j + 2], a2);  b2 = __hfma2(w2, PB[j + 2], b2);
            a3 = __hfma2(w3, PA[j + 3], a3);  b3 = __hfma2(w3, PB[j + 3], b3);
        }
        a0 = __hadd2(__hadd2(a0, a1), __hadd2(a2, a3));
        b0 = __hadd2(__hadd2(b0, b1), __hadd2(b2, b3));
        const float2 fa = __half22float2(a0);
        const float2 fb = __half22float2(b0);
        const float bias = sB[ol];
        const float eA0 = ex2(bias + fa.x), eA1 = ex2(bias + fa.y);
        const float eB0 = ex2(bias + fb.x), eB1 = ex2(bias + fb.y);
        S0 += eA0; S1 += eA1; S2 += eB0; S3 += eB1;
        const __half2 hA = __floats2half2_rn(eA0, eA1);
        const __half2 hB = __floats2half2_rn(eB0, eB1);
        uint2 st;
        st.x = *reinterpret_cast<const unsigned int*>(&hA);
        st.y = *reinterpret_cast<const unsigned int*>(&hB);
        *reinterpret_cast<uint2*>(&g_E[(size_t)(c * KK + ol) * NPIX + pixbase]) = st;
    }
    float4 ps;
    ps.x = S0; ps.y = S1; ps.z = S2; ps.w = S3;
    *reinterpret_cast<float4*>(&g_Spart[(size_t)c * NPIX + pixbase]) = ps;
}

// ================= K2b: reduce 24 partials -> 1/S =================
__global__ void k_sinv() {
    const int idx = blockIdx.x * 256 + threadIdx.x;
    float s = 0.f;
#pragma unroll
    for (int c = 0; c < CC; c++) s += g_Spart[(size_t)c * NPIX + idx];
    g_Sinv[idx] = rcpf(s);
}

// ================= K3..K6: one diffusion iteration (half2 math) =================
#define RROWS 8
#define SROW  (WW + 12)
__global__ __launch_bounds__(256, 4) void k_diff(int srcSel, int dstSel) {
    __shared__ __half hE[RROWS + 6][SROW];   // hE[r][xx] = in(y0+r-3, xx-3), fp16
    __shared__ __half hO[RROWS + 6][SROW];   // hO[r][xx] = hE[r][xx+1]
    const int tid = threadIdx.x;
    const int ty = blockIdx.x;
    const int c = blockIdx.y;
    const int b = blockIdx.z;
    const int y0 = ty * RROWS;
    const int ri = tid >> 6;
    const int x0 = (tid & 63) * 4;

    const float* src = (srcSel == 0) ? g_lat : (srcSel == 1 ? g_dA : g_dB);
    float* dst = (dstSel == 1) ? g_dA : g_dB;

    const float* sp = src + (size_t)(b * CC + c) * PLANE;
    for (int r = 0; r < RROWS + 6; r++) {
        const int yy = y0 + r - 3;
        for (int xx = tid; xx < WW + 8; xx += 256) {
            const int gx = xx - 3;
            const float v = (yy >= 0 && yy < HH && gx >= 0 && gx < WW) ? sp[yy * WW + gx] : 0.f;
            const __half h = __float2half_rn(v);
            hE[r][xx] = h;
            if (xx > 0) hO[r][xx - 1] = h;
        }
    }
    __syncthreads();

    const __half* Eb = g_E + (size_t)(c * KK) * NPIX + (size_t)b * PLANE;
    const float* Sb = g_Sinv + (size_t)b * PLANE;
    float* db = dst + (size_t)(b * CC + c) * PLANE;
    const __half2 Z2 = __float2half2_rn(0.f);

#pragma unroll
    for (int pass = 0; pass < 2; pass++) {
        const int ry = pass * 4 + ri;
        const size_t rowoff = (size_t)(y0 + ry) * WW + x0;
        const __half* Ep = Eb + rowoff;

        __half2 accA[KQ], accB[KQ];
#pragma unroll
        for (int k = 0; k < KQ; k++) { accA[k] = Z2; accB[k] = Z2; }

#pragma unroll
        for (int dy = 0; dy < KQ; dy++) {
            __half2 tE[5], tO[4];
            {
                const uint2 a = *reinterpret_cast<const uint2*>(&hE[ry + dy][x0]);
                const uint2 bq = *reinterpret_cast<const uint2*>(&hE[ry + dy][x0 + 4]);
                const unsigned int cq = *reinterpret_cast<const unsigned int*>(&hE[ry + dy][x0 + 8]);
                *reinterpret_cast<unsigned int*>(&tE[0]) = a.x;
                *reinterpret_cast<unsigned int*>(&tE[1]) = a.y;
                *reinterpret_cast<unsigned int*>(&tE[2]) = bq.x;
                *reinterpret_cast<unsigned int*>(&tE[3]) = bq.y;
                *reinterpret_cast<unsigned int*>(&tE[4]) = cq;
                const uint2 d = *reinterpret_cast<const uint2*>(&hO[ry + dy][x0]);
                const uint2 e2 = *reinterpret_cast<const uint2*>(&hO[ry + dy][x0 + 4]);
                *reinterpret_cast<unsigned int*>(&tO[0]) = d.x;
                *reinterpret_cast<unsigned int*>(&tO[1]) = d.y;
                *reinterpret_cast<unsigned int*>(&tO[2]) = e2.x;
                *reinterpret_cast<unsigned int*>(&tO[3]) = e2.y;
            }
#pragma unroll
            for (int dx = 0; dx < KQ; dx++) {
                const uint2 ev = *reinterpret_cast<const uint2*>(Ep + (size_t)(dy * KQ + dx) * NPIX);
                __half2 eA, eB;
                *reinterpret_cast<unsigned int*>(&eA) = ev.x;
                *reinterpret_cast<unsigned int*>(&eB) = ev.y;
                __half2 p1, p2;
                if ((dx & 1) == 0) { p1 = tE[dx >> 1]; p2 = tE[(dx >> 1) + 1]; }
                else               { p1 = tO[dx >> 1]; p2 = tO[(dx >> 1) + 1]; }
                accA[dx] = __hfma2(eA, p1, accA[dx]);
                accB[dx] = __hfma2(eB, p2, accB[dx]);
            }
        }
        __half2 rA0 = __hadd2(accA[0], accA[1]);
        __half2 rA1 = __hadd2(accA[2], accA[3]);
        __half2 rA2 = __hadd2(accA[4], accA[5]);
        __half2 rA3 = accA[6];
        __half2 rB0 = __hadd2(accB[0], accB[1]);
        __half2 rB1 = __hadd2(accB[2], accB[3]);
        __half2 rB2 = __hadd2(accB[4], accB[5]);
        __half2 rB3 = accB[6];
        const float2 fA0 = __half22float2(rA0), fA1 = __half22float2(rA1);
        const float2 fA2 = __half22float2(rA2), fA3 = __half22float2(rA3);
        const float2 fB0 = __half22float2(rB0), fB1 = __half22float2(rB1);
        const float2 fB2 = __half22float2(rB2), fB3 = __half22float2(rB3);
        const float sumA0 = (fA0.x + fA1.x) + (fA2.x + fA3.x);
        const float sumA1 = (fA0.y + fA1.y) + (fA2.y + fA3.y);
        const float sumB0 = (fB0.x + fB1.x) + (fB2.x + fB3.x);
        const float sumB1 = (fB0.y + fB1.y) + (fB2.y + fB3.y);
        const float4 si = *reinterpret_cast<const float4*>(Sb + rowoff);
        float4 o;
        o.x = sumA0 * si.x;
        o.y = sumA1 * si.y;
        o.z = sumB0 * si.z;
        o.w = sumB1 * si.w;
        *reinterpret_cast<float4*>(db + rowoff) = o;
    }
}

// ================= K7: 1x1 conv (24 -> 1) =================
__global__ void k_out(const float* __restrict__ w_td,
                      const float* __restrict__ b_td,
                      float* __restrict__ out) {
    const int bid = blockIdx.x;
    const int b = bid >> 8, y = bid & 255;
    const int tid = threadIdx.x;
    const float* sp = g_dB + (size_t)b * CC * PLANE + (size_t)y * WW + tid;
    float acc = b_td[0];
#pragma unroll
    for (int c = 0; c < CC; c++) acc = fmaf(w_td[c], sp[(size_t)c * PLANE], acc);
    out[(size_t)b * PLANE + (size_t)y * WW + tid] = acc;
}

// ================= host launcher =================
extern "C" void kernel_launch(void* const* d_in, const int* in_sizes, int n_in,
                              void* d_out, int out_size) {
    const float* depth   = (const float*)d_in[0];
    const float* texture = (const float*)d_in[1];
    const float* w_dp    = (const float*)d_in[2];
    const float* b_dp    = (const float*)d_in[3];
    const float* w_kp    = (const float*)d_in[4];
    const float* b_kp    = (const float*)d_in[5];
    const float* w_td    = (const float*)d_in[6];
    const float* b_td    = (const float*)d_in[7];
    float* out = (float*)d_out;

    k_lat<<<BB * HH, 256>>>(depth, w_dp, b_dp);

    dim3 gs(BB * HH / 2, CC);
    k_softmax<<<gs, 128>>>(texture, w_kp, b_kp);
    k_sinv<<<NPIX / 256, 256>>>();

    dim3 gd(HH / RROWS, CC, BB);
    k_diff<<<gd, 256>>>(0, 1);
    k_diff<<<gd, 256>>>(1, 2);
    k_diff<<<gd, 256>>>(2, 1);
    k_diff<<<gd, 256>>>(1, 2);

    k_out<<<BB * HH, 256>>>(w_td, b_td, out);
}

// round 10
// speedup vs baseline: 1.6131x; 1.1524x over previous
#include <cuda_runtime.h>
#include <cuda_fp16.h>

// ---------------- problem constants ----------------
#define BB   2
#define CC   24
#define KQ   7
#define KK   49
#define HH   256
#define WW   256
#define CO   1176          // CC*KK
#define PLANE 65536
#define NPIX  131072

#define GC   6             // channels per L2-resident diffusion group
#define NGRP (CC / GC)     // 4 groups

#define LOG2E 1.4426950408889634f

// ---------------- device scratch ----------------
__device__ __half g_E[(size_t)CO * NPIX];   // unnormalized exp(logits), fp16, PLANE-MAJOR
__device__ float g_Spart[(size_t)CC * NPIX];
__device__ float g_Sinv[NPIX];
__device__ float g_lat[BB * CC * PLANE];
__device__ float g_dA[BB * CC * PLANE];
__device__ float g_dB[BB * CC * PLANE];

__device__ __forceinline__ float rcpf(float x) {
    float r; asm("rcp.approx.f32 %0, %1;" : "=f"(r) : "f"(x)); return r;
}
__device__ __forceinline__ __half2 ex2h2(__half2 x) {
    unsigned int xi = *reinterpret_cast<unsigned int*>(&x);
    unsigned int ri;
    asm("ex2.approx.f16x2 %0, %1;" : "=r"(ri) : "r"(xi));
    __half2 r;
    *reinterpret_cast<unsigned int*>(&r) = ri;
    return r;
}

// ================= K1: depth_latent = conv3x3(depth; 1 -> 24) =================
__global__ void k_lat(const float* __restrict__ depth,
                      const float* __restrict__ w_dp,
                      const float* __restrict__ b_dp) {
    __shared__ float sD[3][WW + 2];
    __shared__ float sW[CC * 9];
    __shared__ float sB[CC];
    const int bid = blockIdx.x;
    const int b = bid >> 8, y = bid & 255;
    const int tid = threadIdx.x;

    for (int i = tid; i < CC * 9; i += blockDim.x) sW[i] = w_dp[i];
    if (tid < CC) sB[tid] = b_dp[tid];

    const float* dp = depth + (size_t)b * PLANE;
    for (int r = 0; r < 3; r++) {
        const int yy = y + r - 1;
        for (int xx = tid; xx < WW + 2; xx += blockDim.x) {
            const int gx = xx - 1;
            sD[r][xx] = (yy >= 0 && yy < HH && gx >= 0 && gx < WW) ? dp[yy * WW + gx] : 0.f;
        }
    }
    __syncthreads();

    float p[9];
#pragma unroll
    for (int r = 0; r < 3; r++)
#pragma unroll
        for (int cx = 0; cx < 3; cx++) p[r * 3 + cx] = sD[r][tid + cx];

    for (int co = 0; co < CC; co++) {
        float acc = sB[co];
#pragma unroll
        for (int j = 0; j < 9; j++) acc = fmaf(sW[co * 9 + j], p[j], acc);
        g_lat[((size_t)(b * CC + co) * HH + y) * WW + tid] = acc;
    }
}

// ================= K2: logits conv (3->1176) via HFMA2 + f16x2 exp + partial sums =====
__global__ __launch_bounds__(128) void k_softmax(const float* __restrict__ tex,
                                                 const float* __restrict__ w_kp,
                                                 const float* __restrict__ b_kp) {
    __shared__ __align__(16) __half2 sW2h[KK * 28];   // (w,w) half2, 27 + 1 pad per output
    __shared__ __half2 sBh[KK];
    __shared__ __half sTh[3][4][WW + 2];

    const int bid = blockIdx.x;
    const int c = blockIdx.y;
    const int b = bid >> 7;
    const int y0 = (bid & 127) * 2;
    const int tid = threadIdx.x;
    const int ri = tid >> 6;
    const int x0 = (tid & 63) * 4;

    for (int i = tid; i < KK * 28; i += 128) {
        const int o = i / 28, j = i - o * 28;
        const float w = (j < 27) ? w_kp[(size_t)(c * KK + o) * 27 + j] * LOG2E : 0.f;
        const __half h = __float2half_rn(w);
        sW2h[i] = __halves2half2(h, h);
    }
    if (tid < KK) {
        const __half h = __float2half_rn(b_kp[c * KK + tid] * LOG2E);
        sBh[tid] = __halves2half2(h, h);
    }

    for (int ch = 0; ch < 3; ch++) {
        const float* tp = tex + (size_t)(b * 3 + ch) * PLANE;
        for (int rr = 0; rr < 4; rr++) {
            const int yy = y0 + rr - 1;
            for (int xx = tid; xx < WW + 2; xx += blockDim.x) {
                const int gx = xx - 1;
                const float v = (yy >= 0 && yy < HH && gx >= 0 && gx < WW) ? tp[yy * WW + gx] : 0.f;
                sTh[ch][rr][xx] = __float2half_rn(v);
            }
        }
    }
    __syncthreads();

    __half2 PA[28], PB[28];
#pragma unroll
    for (int ch = 0; ch < 3; ch++)
#pragma unroll
        for (int r = 0; r < 3; r++) {
            __half v[6];
#pragma unroll
            for (int k = 0; k < 6; k++) v[k] = sTh[ch][ri + r][x0 + k];
#pragma unroll
            for (int cx = 0; cx < 3; cx++) {
                const int j = ch * 9 + r * 3 + cx;
                PA[j] = __halves2half2(v[cx], v[cx + 1]);
                PB[j] = __halves2half2(v[cx + 2], v[cx + 3]);
            }
        }
    PA[27] = __float2half2_rn(0.f);
    PB[27] = __float2half2_rn(0.f);

    float S0 = 0.f, S1 = 0.f, S2 = 0.f, S3 = 0.f;
    const size_t pixbase = (size_t)b * PLANE + (size_t)(y0 + ri) * WW + x0;
    const __half2 Z2 = __float2half2_rn(0.f);

#pragma unroll 1
    for (int ol = 0; ol < KK; ol++) {
        const uint4* wq = reinterpret_cast<const uint4*>(&sW2h[ol * 28]);
        const __half2 bia = sBh[ol];
        __half2 a0 = bia, a1 = Z2, a2 = Z2, a3 = Z2;
        __half2 b0 = bia, b1 = Z2, b2 = Z2, b3 = Z2;
#pragma unroll
        for (int q = 0; q < 7; q++) {
            const uint4 u = wq[q];
            __half2 w0, w1, w2, w3;
            *reinterpret_cast<unsigned int*>(&w0) = u.x;
            *reinterpret_cast<unsigned int*>(&w1) = u.y;
            *reinterpret_cast<unsigned int*>(&w2) = u.z;
            *reinterpret_cast<unsigned int*>(&w3) = u.w;
            const int j = q * 4;
            a0 = __hfma2(w0, PA[j],     a0);  b0 = __hfma2(w0, PB[j],     b0);
            a1 = __hfma2(w1, PA[j + 1], a1);  b1 = __hfma2(w1, PB[j + 1], b1);
            a2 = __hfma2(w2, PA[j + 2], a2);  b2 = __hfma2(w2, PB[j + 2], b2);
            a3 = __hfma2(w3, PA[j + 3], a3);  b3 = __hfma2(w3, PB[j + 3], b3);
        }
        a0 = __hadd2(__hadd2(a0, a1), __hadd2(a2, a3));
        b0 = __hadd2(__hadd2(b0, b1), __hadd2(b2, b3));
        const __half2 eA = ex2h2(a0);        // E stored exactly as these half values
        const __half2 eB = ex2h2(b0);
        const float2 fA = __half22float2(eA);
        const float2 fB = __half22float2(eB);
        S0 += fA.x; S1 += fA.y; S2 += fB.x; S3 += fB.y;
        uint2 st;
        st.x = *reinterpret_cast<const unsigned int*>(&eA);
        st.y = *reinterpret_cast<const unsigned int*>(&eB);
        *reinterpret_cast<uint2*>(&g_E[(size_t)(c * KK + ol) * NPIX + pixbase]) = st;
    }
    float4 ps;
    ps.x = S0; ps.y = S1; ps.z = S2; ps.w = S3;
    *reinterpret_cast<float4*>(&g_Spart[(size_t)c * NPIX + pixbase]) = ps;
}

// ================= K2b: reduce 24 partials -> 1/S =================
__global__ void k_sinv() {
    const int idx = blockIdx.x * 256 + threadIdx.x;
    float s = 0.f;
#pragma unroll
    for (int c = 0; c < CC; c++) s += g_Spart[(size_t)c * NPIX + idx];
    g_Sinv[idx] = rcpf(s);
}

// ================= K3..: one diffusion iteration over a 6-channel group ==========
// grid (HH/RROWS, GC, BB); channel = c0 + blockIdx.y. Group's E (77MB) stays in L2
// across the 4 iteration launches.
#define RROWS 8
#define SROW  (WW + 12)
__global__ __launch_bounds__(256, 4) void k_diff(int srcSel, int dstSel, int c0) {
    __shared__ __half hE[RROWS + 6][SROW];
    __shared__ __half hO[RROWS + 6][SROW];
    const int tid = threadIdx.x;
    const int ty = blockIdx.x;
    const int c = c0 + blockIdx.y;
    const int b = blockIdx.z;
    const int y0 = ty * RROWS;
    const int ri = tid >> 6;
    const int x0 = (tid & 63) * 4;

    const float* src = (srcSel == 0) ? g_lat : (srcSel == 1 ? g_dA : g_dB);
    float* dst = (dstSel == 1) ? g_dA : g_dB;

    const float* sp = src + (size_t)(b * CC + c) * PLANE;
    for (int r = 0; r < RROWS + 6; r++) {
        const int yy = y0 + r - 3;
        for (int xx = tid; xx < WW + 8; xx += 256) {
            const int gx = xx - 3;
            const float v = (yy >= 0 && yy < HH && gx >= 0 && gx < WW) ? sp[yy * WW + gx] : 0.f;
            const __half h = __float2half_rn(v);
            hE[r][xx] = h;
            if (xx > 0) hO[r][xx - 1] = h;
        }
    }
    __syncthreads();

    const __half* Eb = g_E + (size_t)(c * KK) * NPIX + (size_t)b * PLANE;
    const float* Sb = g_Sinv + (size_t)b * PLANE;
    float* db = dst + (size_t)(b * CC + c) * PLANE;
    const __half2 Z2 = __float2half2_rn(0.f);

#pragma unroll
    for (int pass = 0; pass < 2; pass++) {
        const int ry = pass * 4 + ri;
        const size_t rowoff = (size_t)(y0 + ry) * WW + x0;
        const __half* Ep = Eb + rowoff;

        __half2 accA[KQ], accB[KQ];
#pragma unroll
        for (int k = 0; k < KQ; k++) { accA[k] = Z2; accB[k] = Z2; }

#pragma unroll
        for (int dy = 0; dy < KQ; dy++) {
            __half2 tE[5], tO[4];
            {
                const uint2 a = *reinterpret_cast<const uint2*>(&hE[ry + dy][x0]);
                const uint2 bq = *reinterpret_cast<const uint2*>(&hE[ry + dy][x0 + 4]);
                const unsigned int cq = *reinterpret_cast<const unsigned int*>(&hE[ry + dy][x0 + 8]);
                *reinterpret_cast<unsigned int*>(&tE[0]) = a.x;
                *reinterpret_cast<unsigned int*>(&tE[1]) = a.y;
                *reinterpret_cast<unsigned int*>(&tE[2]) = bq.x;
                *reinterpret_cast<unsigned int*>(&tE[3]) = bq.y;
                *reinterpret_cast<unsigned int*>(&tE[4]) = cq;
                const uint2 d = *reinterpret_cast<const uint2*>(&hO[ry + dy][x0]);
                const uint2 e2 = *reinterpret_cast<const uint2*>(&hO[ry + dy][x0 + 4]);
                *reinterpret_cast<unsigned int*>(&tO[0]) = d.x;
                *reinterpret_cast<unsigned int*>(&tO[1]) = d.y;
                *reinterpret_cast<unsigned int*>(&tO[2]) = e2.x;
                *reinterpret_cast<unsigned int*>(&tO[3]) = e2.y;
            }
#pragma unroll
            for (int dx = 0; dx < KQ; dx++) {
                const uint2 ev = *reinterpret_cast<const uint2*>(Ep + (size_t)(dy * KQ + dx) * NPIX);
                __half2 eA, eB;
                *reinterpret_cast<unsigned int*>(&eA) = ev.x;
                *reinterpret_cast<unsigned int*>(&eB) = ev.y;
                __half2 p1, p2;
                if ((dx & 1) == 0) { p1 = tE[dx >> 1]; p2 = tE[(dx >> 1) + 1]; }
                else               { p1 = tO[dx >> 1]; p2 = tO[(dx >> 1) + 1]; }
                accA[dx] = __hfma2(eA, p1, accA[dx]);
                accB[dx] = __hfma2(eB, p2, accB[dx]);
            }
        }
        __half2 rA0 = __hadd2(accA[0], accA[1]);
        __half2 rA1 = __hadd2(accA[2], accA[3]);
        __half2 rA2 = __hadd2(accA[4], accA[5]);
        __half2 rA3 = accA[6];
        __half2 rB0 = __hadd2(accB[0], accB[1]);
        __half2 rB1 = __hadd2(accB[2], accB[3]);
        __half2 rB2 = __hadd2(accB[4], accB[5]);
        __half2 rB3 = accB[6];
        const float2 fA0 = __half22float2(rA0), fA1 = __half22float2(rA1);
        const float2 fA2 = __half22float2(rA2), fA3 = __half22float2(rA3);
        const float2 fB0 = __half22float2(rB0), fB1 = __half22float2(rB1);
        const float2 fB2 = __half22float2(rB2), fB3 = __half22float2(rB3);
        const float sumA0 = (fA0.x + fA1.x) + (fA2.x + fA3.x);
        const float sumA1 = (fA0.y + fA1.y) + (fA2.y + fA3.y);
        const float sumB0 = (fB0.x + fB1.x) + (fB2.x + fB3.x);
        const float sumB1 = (fB0.y + fB1.y) + (fB2.y + fB3.y);
        const float4 si = *reinterpret_cast<const float4*>(Sb + rowoff);
        float4 o;
        o.x = sumA0 * si.x;
        o.y = sumA1 * si.y;
        o.z = sumB0 * si.z;
        o.w = sumB1 * si.w;
        *reinterpret_cast<float4*>(db + rowoff) = o;
    }
}

// ================= K7: 1x1 conv (24 -> 1) =================
__global__ void k_out(const float* __restrict__ w_td,
                      const float* __restrict__ b_td,
                      float* __restrict__ out) {
    const int bid = blockIdx.x;
    const int b = bid >> 8, y = bid & 255;
    const int tid = threadIdx.x;
    const float* sp = g_dB + (size_t)b * CC * PLANE + (size_t)y * WW + tid;
    float acc = b_td[0];
#pragma unroll
    for (int c = 0; c < CC; c++) acc = fmaf(w_td[c], sp[(size_t)c * PLANE], acc);
    out[(size_t)b * PLANE + (size_t)y * WW + tid] = acc;
}

// ================= host launcher =================
extern "C" void kernel_launch(void* const* d_in, const int* in_sizes, int n_in,
                              void* d_out, int out_size) {
    const float* depth   = (const float*)d_in[0];
    const float* texture = (const float*)d_in[1];
    const float* w_dp    = (const float*)d_in[2];
    const float* b_dp    = (const float*)d_in[3];
    const float* w_kp    = (const float*)d_in[4];
    const float* b_kp    = (const float*)d_in[5];
    const float* w_td    = (const float*)d_in[6];
    const float* b_td    = (const float*)d_in[7];
    float* out = (float*)d_out;

    k_lat<<<BB * HH, 256>>>(depth, w_dp, b_dp);

    dim3 gs(BB * HH / 2, CC);
    k_softmax<<<gs, 128>>>(texture, w_kp, b_kp);
    k_sinv<<<NPIX / 256, 256>>>();

    // L2-resident channel groups: all 4 iterations of a group back-to-back.
    // Descending order so the last-written E (still in L2) is consumed first.
    dim3 gd(HH / RROWS, GC, BB);
    for (int g = NGRP - 1; g >= 0; g--) {
        const int c0 = g * GC;
        k_diff<<<gd, 256>>>(0, 1, c0);   // lat -> dA
        k_diff<<<gd, 256>>>(1, 2, c0);   // dA  -> dB
        k_diff<<<gd, 256>>>(2, 1, c0);   // dB  -> dA
        k_diff<<<gd, 256>>>(1, 2, c0);   // dA  -> dB
    }

    k_out<<<BB * HH, 256>>>(w_td, b_td, out);
}